// round 14
// baseline (speedup 1.0000x reference)
#include <cuda_runtime.h>
#include <cuda_fp16.h>
#include <cstdint>

// ---------------- problem constants ----------------
#define S_LEN   4096
#define NHEADS  16
#define DQK     192
#define DNOPE   128
#define DROPE   64
#define DV      128
#define DIM_IN  2048
#define KV_LORA 512
#define KV_TOT  576
#define QDIM    (NHEADS*DQK)         // 3072
#define UPDIM   (NHEADS*(DNOPE+DV))  // 4096
#define ODIM    (NHEADS*DV)          // 2048
#define SOFTMAX_SCALE 0.13522975134194065f
#define SCALE_LOG2E 0.19510458386472476f

// ---------------- half scratch (device globals) ----------------
__device__ __half g_hx   [(size_t)S_LEN*DIM_IN];
__device__ __half g_hwq  [(size_t)DIM_IN*QDIM];
__device__ __half g_hwkva[(size_t)DIM_IN*KV_TOT];
__device__ __half g_hwkvb[(size_t)KV_LORA*UPDIM];
__device__ __half g_hwo  [(size_t)ODIM*DIM_IN];
__device__ __half g_hq   [(size_t)S_LEN*QDIM];
__device__ __half g_hkv  [(size_t)S_LEN*KV_TOT];
__device__ __half g_hkvn [(size_t)S_LEN*KV_LORA];
__device__ __half g_hkpe [(size_t)S_LEN*DROPE];
__device__ __half g_hkvup[(size_t)S_LEN*UPDIM];
__device__ __half g_hattn[(size_t)S_LEN*ODIM];

// ---------------- helpers ----------------
__device__ __forceinline__ uint32_t sm_u32(const void* p) {
    return (uint32_t)__cvta_generic_to_shared(p);
}
__device__ __forceinline__ void cp16(void* dst, const void* src) {
    asm volatile("cp.async.ca.shared.global [%0], [%1], 16;"
                 :: "r"(sm_u32(dst)), "l"(src));
}
__device__ __forceinline__ void cp_commit() { asm volatile("cp.async.commit_group;"); }
template<int N> __device__ __forceinline__ void cp_wait() {
    asm volatile("cp.async.wait_group %0;" :: "n"(N));
}
__device__ __forceinline__ void ldsm4(uint32_t* r, uint32_t a) {
    asm volatile("ldmatrix.sync.aligned.m8n8.x4.shared.b16 {%0,%1,%2,%3}, [%4];"
        : "=r"(r[0]), "=r"(r[1]), "=r"(r[2]), "=r"(r[3]) : "r"(a));
}
__device__ __forceinline__ void ldsm4t(uint32_t* r, uint32_t a) {
    asm volatile("ldmatrix.sync.aligned.m8n8.x4.trans.shared.b16 {%0,%1,%2,%3}, [%4];"
        : "=r"(r[0]), "=r"(r[1]), "=r"(r[2]), "=r"(r[3]) : "r"(a));
}
__device__ __forceinline__ void mma_f16(float* d, const uint32_t* a, const uint32_t* b) {
    asm volatile("mma.sync.aligned.m16n8k16.row.col.f32.f16.f16.f32 "
        "{%0,%1,%2,%3}, {%4,%5,%6,%7}, {%8,%9}, {%0,%1,%2,%3};\n"
        : "+f"(d[0]), "+f"(d[1]), "+f"(d[2]), "+f"(d[3])
        : "r"(a[0]), "r"(a[1]), "r"(a[2]), "r"(a[3]), "r"(b[0]), "r"(b[1]));
}
__device__ __forceinline__ uint32_t h2u(__half2 h) {
    return *reinterpret_cast<uint32_t*>(&h);
}
__device__ __forceinline__ float ex2(float x) {
    float y;
    asm("ex2.approx.ftz.f32 %0, %1;" : "=f"(y) : "f"(x));
    return y;
}

// ---------------- fp32 -> fp16 convert ----------------
__global__ void f2h_kernel(const float* __restrict__ in, __half* __restrict__ out, int n) {
    int i = (blockIdx.x * blockDim.x + threadIdx.x) * 4;
    if (i >= n) return;
    float4 v = *reinterpret_cast<const float4*>(&in[i]);
    __half2 a = __floats2half2_rn(v.x, v.y);
    __half2 b = __floats2half2_rn(v.z, v.w);
    uint2 p;
    p.x = *reinterpret_cast<uint32_t*>(&a);
    p.y = *reinterpret_cast<uint32_t*>(&b);
    *reinterpret_cast<uint2*>(&out[i]) = p;
}

// ---------------- HGEMM: 128x128 tile, 8 warps (4M x 2N) of 32x64 ----------------
#define GAP 40
#define GBP 136
struct HGemmSm {
    __half As[4][128][GAP];
    __half Bs[4][32][GBP];
};

template<bool HALF_OUT, bool DO_ROPE>
__global__ __launch_bounds__(256, 2) void hgemm(
    const __half* __restrict__ A, const __half* __restrict__ B,
    void* __restrict__ Cout, int M, int N, int K,
    const float* __restrict__ FC, const float* __restrict__ FS)
{
    extern __shared__ char smraw[];
    HGemmSm& sm = *reinterpret_cast<HGemmSm*>(smraw);
    const int tid = threadIdx.x, lane = tid & 31, warp = tid >> 5;
    const int wm = warp & 3, wn = warp >> 2;
    const int g = lane >> 2, tig = lane & 3;
    const int m0 = blockIdx.y * 128, n0 = blockIdx.x * 128;

    float acc[2][8][4];
    #pragma unroll
    for (int i = 0; i < 2; i++)
        #pragma unroll
        for (int j = 0; j < 8; j++)
            #pragma unroll
            for (int k = 0; k < 4; k++) acc[i][j][k] = 0.f;

    auto load = [&](int t, int st) {
        const int k0 = t * 32;
        #pragma unroll
        for (int r = 0; r < 2; r++) {
            int c = tid + r * 256;
            int row = c >> 2, kc = (c & 3) * 8;
            cp16(&sm.As[st][row][kc], &A[(size_t)(m0 + row) * K + k0 + kc]);
        }
        #pragma unroll
        for (int r = 0; r < 2; r++) {
            int c = tid + r * 256;
            int kr = c >> 4, nc = (c & 15) * 8;
            int col = n0 + nc;
            if (col < N)
                cp16(&sm.Bs[st][kr][nc], &B[(size_t)(k0 + kr) * N + col]);
            else {
                uint4 z = make_uint4(0, 0, 0, 0);
                *reinterpret_cast<uint4*>(&sm.Bs[st][kr][nc]) = z;
            }
        }
        cp_commit();
    };

    const int nt = K / 32;
    load(0, 0); load(1, 1); load(2, 2);

    for (int t = 0; t < nt; t++) {
        cp_wait<2>();
        __syncthreads();
        if (t + 3 < nt) load(t + 3, (t + 3) & 3);
        else            cp_commit();
        const int st = t & 3;

        #pragma unroll
        for (int ks = 0; ks < 32; ks += 16) {
            uint32_t af[2][4];
            #pragma unroll
            for (int mf = 0; mf < 2; mf++) {
                int row = wm * 32 + mf * 16 + (lane & 7) + ((lane >> 3) & 1) * 8;
                int col = ks + (lane >> 4) * 8;
                ldsm4(af[mf], sm_u32(&sm.As[st][row][col]));
            }
            #pragma unroll
            for (int np = 0; np < 4; np++) {
                uint32_t bb[4];
                int row = ks + (lane & 7) + ((lane >> 3) & 1) * 8;
                int col = wn * 64 + np * 16 + ((lane >> 4) & 1) * 8;
                ldsm4t(bb, sm_u32(&sm.Bs[st][row][col]));
                int nf = np * 2;
                mma_f16(acc[0][nf],     af[0], bb);
                mma_f16(acc[1][nf],     af[1], bb);
                mma_f16(acc[0][nf + 1], af[0], bb + 2);
                mma_f16(acc[1][nf + 1], af[1], bb + 2);
            }
        }
    }

    #pragma unroll
    for (int mf = 0; mf < 2; mf++) {
        #pragma unroll
        for (int nf = 0; nf < 8; nf++) {
            int r = m0 + wm * 32 + mf * 16 + g;
            int c = n0 + wn * 64 + nf * 8 + tig * 2;
            if (c < N) {
                float a0 = acc[mf][nf][0], a1 = acc[mf][nf][1];
                float a2 = acc[mf][nf][2], a3 = acc[mf][nf][3];
                if (DO_ROPE) {
                    int d = c % DQK;
                    if (d >= DNOPE) {
                        int p = (d - DNOPE) >> 1;
                        float c0 = FC[r * 32 + p],       s0 = FS[r * 32 + p];
                        float c1 = FC[(r + 8) * 32 + p], s1 = FS[(r + 8) * 32 + p];
                        float t0 = a0 * c0 - a1 * s0, t1 = a0 * s0 + a1 * c0;
                        float t2 = a2 * c1 - a3 * s1, t3 = a2 * s1 + a3 * c1;
                        a0 = t0; a1 = t1; a2 = t2; a3 = t3;
                    }
                }
                if (HALF_OUT) {
                    __half* C = (__half*)Cout;
                    *reinterpret_cast<__half2*>(&C[(size_t)r * N + c]) =
                        __floats2half2_rn(a0, a1);
                    *reinterpret_cast<__half2*>(&C[(size_t)(r + 8) * N + c]) =
                        __floats2half2_rn(a2, a3);
                } else {
                    float* C = (float*)Cout;
                    *reinterpret_cast<float2*>(&C[(size_t)r * N + c]) = make_float2(a0, a1);
                    *reinterpret_cast<float2*>(&C[(size_t)(r + 8) * N + c]) = make_float2(a2, a3);
                }
            }
        }
    }
}

// ---------------- rmsnorm + rope(k_pe) (half io) ----------------
__global__ void kvnorm_kernel(const __half* __restrict__ KV,
                              const float* __restrict__ W,
                              const float* __restrict__ C,
                              const float* __restrict__ Sn,
                              __half* __restrict__ KVN,
                              __half* __restrict__ KPE)
{
    int s = blockIdx.x;
    int tid = threadIdx.x;
    const __half* row = KV + (size_t)s * KV_TOT;

    float ss = 0.f;
    for (int i = tid; i < KV_LORA; i += 256) {
        float v = __half2float(row[i]); ss += v * v;
    }
    __shared__ float red[256];
    red[tid] = ss;
    __syncthreads();
    for (int off = 128; off > 0; off >>= 1) {
        if (tid < off) red[tid] += red[tid + off];
        __syncthreads();
    }
    __shared__ float rinv;
    if (tid == 0) rinv = rsqrtf(red[0] * (1.0f / KV_LORA) + 1e-6f);
    __syncthreads();
    float r = rinv;
    for (int i = tid; i < KV_LORA; i += 256)
        KVN[(size_t)s * KV_LORA + i] = __float2half_rn(__half2float(row[i]) * r * W[i]);

    if (tid < 32) {
        int p = tid;
        float xr = __half2float(row[KV_LORA + 2 * p]);
        float xi = __half2float(row[KV_LORA + 2 * p + 1]);
        float c = C[s * 32 + p], sn = Sn[s * 32 + p];
        *reinterpret_cast<__half2*>(&KPE[(size_t)s * DROPE + 2 * p]) =
            __floats2half2_rn(xr * c - xi * sn, xr * sn + xi * c);
    }
}

// ---------------- flash attention v7: BM=128, BN=128 (half the iterations) ----------------
#define BM 128
#define BN 128
#define QKP 200
#define VSP 136

struct AttnSm {
    __half Qt[BM][QKP];       // 51200 B
    __half Kt[2][BN][QKP];    // 102400 B
    __half Vs[2][BN][VSP];    // 69632 B  -> 223232 B
};

__global__ __launch_bounds__(256, 1) void attn_f16(
    const __half* __restrict__ Q,
    const __half* __restrict__ KVUP,
    const __half* __restrict__ KPE,
    __half* __restrict__ O)
{
    extern __shared__ char smraw[];
    AttnSm& sm = *reinterpret_cast<AttnSm*>(smraw);
    const int tid = threadIdx.x, lane = tid & 31, warp = tid >> 5;
    const int g = lane >> 2, tig = lane & 3;
    const int qb = (int)gridDim.x - 1 - (int)blockIdx.x;
    const int h  = blockIdx.y;
    const int qs0 = qb * BM;

    auto load_kv = [&](int kb, int buf) {
        const int ks0 = kb * BN;
        #pragma unroll
        for (int r = 0; r < 12; r++) {           // K: 128 rows x 24 chunks = 3072
            int c = tid + r * 256;
            int n = c / 24, dc = c % 24;
            if (dc < 16)
                cp16(&sm.Kt[buf][n][dc * 8],
                     &KVUP[(size_t)(ks0 + n) * UPDIM + h * 256 + dc * 8]);
            else
                cp16(&sm.Kt[buf][n][128 + (dc - 16) * 8],
                     &KPE[(size_t)(ks0 + n) * DROPE + (dc - 16) * 8]);
        }
        #pragma unroll
        for (int r = 0; r < 8; r++) {            // V: 128 rows x 16 chunks = 2048
            int c = tid + r * 256;
            int n = c >> 4, dc = c & 15;
            cp16(&sm.Vs[buf][n][dc * 8],
                 &KVUP[(size_t)(ks0 + n) * UPDIM + h * 256 + 128 + dc * 8]);
        }
        cp_commit();
    };

    // stage Q tile + first KV block
    for (int c = tid; c < BM * 24; c += 256) {
        int m = c / 24, dc = c % 24;
        cp16(&sm.Qt[m][dc * 8], &Q[(size_t)(qs0 + m) * QDIM + h * DQK + dc * 8]);
    }
    cp_commit();
    load_kv(0, 0);
    cp_wait<0>();
    __syncthreads();

    // hoist Q fragments to registers
    uint32_t qf[DQK / 16][4];
    #pragma unroll
    for (int ks = 0; ks < DQK / 16; ks++) {
        int row = warp * 16 + (lane & 7) + ((lane >> 3) & 1) * 8;
        int col = ks * 16 + (lane >> 4) * 8;
        ldsm4(qf[ks], sm_u32(&sm.Qt[row][col]));
    }

    const int rl = warp * 16 + g;
    const int rg0 = qs0 + rl, rg1 = rg0 + 8;
    float r_m0 = -3.0e38f, r_m1 = -3.0e38f;
    float r_l0 = 0.f, r_l1 = 0.f;

    float o_acc[16][4];
    #pragma unroll
    for (int j = 0; j < 16; j++)
        #pragma unroll
        for (int k = 0; k < 4; k++) o_acc[j][k] = 0.f;

    const int nkb = qb + 1;                      // 128-wide key blocks
    for (int kb = 0; kb < nkb; kb++) {
        const int buf = kb & 1;
        const int ks0 = kb * BN;
        if (kb > 0) { cp_wait<0>(); __syncthreads(); }
        if (kb + 1 < nkb) load_kv(kb + 1, buf ^ 1);

        // ---- GEMM1: S = Q K^T, warp tile 16(M) x 128(N) ----
        float s_acc[16][4];
        #pragma unroll
        for (int j = 0; j < 16; j++)
            #pragma unroll
            for (int k = 0; k < 4; k++) s_acc[j][k] = 0.f;

        #pragma unroll
        for (int ks = 0; ks < DQK / 16; ks++) {
            uint32_t kf[32];
            #pragma unroll
            for (int np = 0; np < 8; np++) {
                int row = np * 16 + ((lane >> 4) & 1) * 8 + (lane & 7);
                int col = ks * 16 + ((lane >> 3) & 1) * 8;
                ldsm4(kf + np * 4, sm_u32(&sm.Kt[buf][row][col]));
            }
            #pragma unroll
            for (int np = 0; np < 8; np++) {
                mma_f16(s_acc[np * 2],     qf[ks], kf + np * 4);
                mma_f16(s_acc[np * 2 + 1], qf[ks], kf + np * 4 + 2);
            }
        }

        // ---- V prefetch (half-chunk 0) before softmax ----
        auto ldV = [&](int hc, uint32_t* dst) {
            int ks = hc >> 1, nh = hc & 1;
            #pragma unroll
            for (int j = 0; j < 4; j++) {
                int np = nh * 4 + j;
                int row = ks * 16 + (lane & 7) + ((lane >> 3) & 1) * 8;
                int col = np * 16 + ((lane >> 4) & 1) * 8;
                ldsm4t(dst + j * 4, sm_u32(&sm.Vs[buf][row][col]));
            }
        };
        uint32_t vf[2][16];
        ldV(0, vf[0]);

        // ---- scale to log2 domain; mask only in the diagonal block ----
        #pragma unroll
        for (int nf = 0; nf < 16; nf++) {
            s_acc[nf][0] *= SCALE_LOG2E;
            s_acc[nf][1] *= SCALE_LOG2E;
            s_acc[nf][2] *= SCALE_LOG2E;
            s_acc[nf][3] *= SCALE_LOG2E;
        }
        if (kb == nkb - 1) {
            #pragma unroll
            for (int nf = 0; nf < 16; nf++) {
                int cg = ks0 + nf * 8 + tig * 2;
                if (cg     > rg0) s_acc[nf][0] = -1.0e30f;
                if (cg + 1 > rg0) s_acc[nf][1] = -1.0e30f;
                if (cg     > rg1) s_acc[nf][2] = -1.0e30f;
                if (cg + 1 > rg1) s_acc[nf][3] = -1.0e30f;
            }
        }

        // ---- warp-local online softmax (log2 domain) ----
        float mx0 = -3.0e38f, mx1 = -3.0e38f;
        #pragma unroll
        for (int nf = 0; nf < 16; nf++) {
            mx0 = fmaxf(mx0, fmaxf(s_acc[nf][0], s_acc[nf][1]));
            mx1 = fmaxf(mx1, fmaxf(s_acc[nf][2], s_acc[nf][3]));
        }
        mx0 = fmaxf(mx0, __shfl_xor_sync(0xffffffffu, mx0, 1));
        mx0 = fmaxf(mx0, __shfl_xor_sync(0xffffffffu, mx0, 2));
        mx1 = fmaxf(mx1, __shfl_xor_sync(0xffffffffu, mx1, 1));
        mx1 = fmaxf(mx1, __shfl_xor_sync(0xffffffffu, mx1, 2));

        float nm0 = fmaxf(r_m0, mx0), nm1 = fmaxf(r_m1, mx1);
        float a0 = ex2(r_m0 - nm0), a1 = ex2(r_m1 - nm1);
        r_m0 = nm0; r_m1 = nm1;

        uint32_t pa[8][4];
        float sum0 = 0.f, sum1 = 0.f;
        #pragma unroll
        for (int nf = 0; nf < 16; nf++) {
            float p0 = ex2(s_acc[nf][0] - nm0);
            float p1 = ex2(s_acc[nf][1] - nm0);
            float p2 = ex2(s_acc[nf][2] - nm1);
            float p3 = ex2(s_acc[nf][3] - nm1);
            sum0 += p0 + p1; sum1 += p2 + p3;
            pa[nf >> 1][(nf & 1) * 2 + 0] = h2u(__floats2half2_rn(p0, p1));
            pa[nf >> 1][(nf & 1) * 2 + 1] = h2u(__floats2half2_rn(p2, p3));
        }
        sum0 += __shfl_xor_sync(0xffffffffu, sum0, 1);
        sum0 += __shfl_xor_sync(0xffffffffu, sum0, 2);
        sum1 += __shfl_xor_sync(0xffffffffu, sum1, 1);
        sum1 += __shfl_xor_sync(0xffffffffu, sum1, 2);
        r_l0 = r_l0 * a0 + sum0;
        r_l1 = r_l1 * a1 + sum1;

        // ---- GEMM2: O = alpha*O + P V over 128 keys, pipelined V half-chunks ----
        #pragma unroll
        for (int nf = 0; nf < 16; nf++) {
            o_acc[nf][0] *= a0; o_acc[nf][1] *= a0;
            o_acc[nf][2] *= a1; o_acc[nf][3] *= a1;
        }
        #pragma unroll
        for (int hc = 0; hc < 16; hc++) {
            const int cur = hc & 1;
            if (hc + 1 < 16) ldV(hc + 1, vf[cur ^ 1]);
            const int ks = hc >> 1, nh = hc & 1;
            #pragma unroll
            for (int j = 0; j < 4; j++) {
                int np = nh * 4 + j;
                mma_f16(o_acc[np * 2],     pa[ks], vf[cur] + j * 4);
                mma_f16(o_acc[np * 2 + 1], pa[ks], vf[cur] + j * 4 + 2);
            }
        }
    }

    float inv0 = 1.0f / r_l0, inv1 = 1.0f / r_l1;
    #pragma unroll
    for (int nf = 0; nf < 16; nf++) {
        int col = h * DV + nf * 8 + tig * 2;
        *reinterpret_cast<__half2*>(&O[(size_t)rg0 * ODIM + col]) =
            __floats2half2_rn(o_acc[nf][0] * inv0, o_acc[nf][1] * inv0);
        *reinterpret_cast<__half2*>(&O[(size_t)rg1 * ODIM + col]) =
            __floats2half2_rn(o_acc[nf][2] * inv1, o_acc[nf][3] * inv1);
    }
}

// ---------------- persistent stream/event holder ----------------
struct ForkCtx {
    cudaStream_t sA = 0, sB = 0;
    cudaEvent_t  eFork = 0, eX = 0, eWkvb = 0, eWo = 0, eKV = 0;
    bool ok = false;
    ForkCtx() {
        ok = (cudaStreamCreateWithFlags(&sA, cudaStreamNonBlocking) == cudaSuccess) &&
             (cudaStreamCreateWithFlags(&sB, cudaStreamNonBlocking) == cudaSuccess) &&
             (cudaEventCreateWithFlags(&eFork, cudaEventDisableTiming) == cudaSuccess) &&
             (cudaEventCreateWithFlags(&eX,    cudaEventDisableTiming) == cudaSuccess) &&
             (cudaEventCreateWithFlags(&eWkvb, cudaEventDisableTiming) == cudaSuccess) &&
             (cudaEventCreateWithFlags(&eWo,   cudaEventDisableTiming) == cudaSuccess) &&
             (cudaEventCreateWithFlags(&eKV,   cudaEventDisableTiming) == cudaSuccess);
    }
};

// ---------------- launcher: multi-stream fork/join inside graph capture ----------------
extern "C" void kernel_launch(void* const* d_in, const int* in_sizes, int n_in,
                              void* d_out, int out_size)
{
    (void)in_sizes; (void)n_in; (void)out_size;
    const float* x    = (const float*)d_in[0];
    const float* fc   = (const float*)d_in[1];
    const float* fs   = (const float*)d_in[2];
    const float* wq   = (const float*)d_in[4];
    const float* wkva = (const float*)d_in[5];
    const float* kvw  = (const float*)d_in[6];
    const float* wkvb = (const float*)d_in[7];
    const float* wo   = (const float*)d_in[8];
    float* out = (float*)d_out;

    __half *hx, *hwq, *hwkva, *hwkvb, *hwo, *hq, *hkv, *hkvn, *hkpe, *hkvup, *hattn;
    cudaGetSymbolAddress((void**)&hx,    g_hx);
    cudaGetSymbolAddress((void**)&hwq,   g_hwq);
    cudaGetSymbolAddress((void**)&hwkva, g_hwkva);
    cudaGetSymbolAddress((void**)&hwkvb, g_hwkvb);
    cudaGetSymbolAddress((void**)&hwo,   g_hwo);
    cudaGetSymbolAddress((void**)&hq,    g_hq);
    cudaGetSymbolAddress((void**)&hkv,   g_hkv);
    cudaGetSymbolAddress((void**)&hkvn,  g_hkvn);
    cudaGetSymbolAddress((void**)&hkpe,  g_hkpe);
    cudaGetSymbolAddress((void**)&hkvup, g_hkvup);
    cudaGetSymbolAddress((void**)&hattn, g_hattn);

    cudaFuncSetAttribute((const void*)hgemm<true, false>,
        cudaFuncAttributeMaxDynamicSharedMemorySize, (int)sizeof(HGemmSm));
    cudaFuncSetAttribute((const void*)hgemm<true, true>,
        cudaFuncAttributeMaxDynamicSharedMemorySize, (int)sizeof(HGemmSm));
    cudaFuncSetAttribute((const void*)hgemm<false, false>,
        cudaFuncAttributeMaxDynamicSharedMemorySize, (int)sizeof(HGemmSm));
    cudaFuncSetAttribute((const void*)attn_f16,
        cudaFuncAttributeMaxDynamicSharedMemorySize, (int)sizeof(AttnSm));

    static ForkCtx fx;
    const bool forked = fx.ok;
    cudaStream_t sA = forked ? fx.sA : 0;
    cudaStream_t sB = forked ? fx.sB : 0;

    if (forked) {
        cudaEventRecord(fx.eFork, 0);
        cudaStreamWaitEvent(sA, fx.eFork, 0);
        cudaStreamWaitEvent(sB, fx.eFork, 0);
    }

    // ---- stream 0: x convert + Q path (rope fused into q projection) ----
    f2h_kernel<<<(S_LEN*DIM_IN) / 1024, 256, 0, 0>>>(x, hx, S_LEN*DIM_IN);
    if (forked) cudaEventRecord(fx.eX, 0);
    f2h_kernel<<<(DIM_IN*QDIM) / 1024, 256, 0, 0>>>(wq, hwq, DIM_IN*QDIM);
    hgemm<true, true><<<dim3(QDIM / 128, S_LEN / 128), 256, sizeof(HGemmSm), 0>>>(
        hx, hwq, hq, S_LEN, QDIM, DIM_IN, fc, fs);

    // ---- stream B: independent weight conversions ----
    f2h_kernel<<<(KV_LORA*UPDIM) / 1024, 256, 0, sB>>>(wkvb, hwkvb, KV_LORA*UPDIM);
    if (forked) cudaEventRecord(fx.eWkvb, sB);
    f2h_kernel<<<(ODIM*DIM_IN) / 1024, 256, 0, sB>>>(wo, hwo, ODIM*DIM_IN);
    if (forked) cudaEventRecord(fx.eWo, sB);

    // ---- stream A: KV path ----
    f2h_kernel<<<(DIM_IN*KV_TOT) / 1024, 256, 0, sA>>>(wkva, hwkva, DIM_IN*KV_TOT);
    if (forked) cudaStreamWaitEvent(sA, fx.eX, 0);
    hgemm<true, false><<<dim3((KV_TOT + 127) / 128, S_LEN / 128), 256, sizeof(HGemmSm), sA>>>(
        hx, hwkva, hkv, S_LEN, KV_TOT, DIM_IN, nullptr, nullptr);
    kvnorm_kernel<<<S_LEN, 256, 0, sA>>>(hkv, kvw, fc, fs, hkvn, hkpe);
    if (forked) cudaStreamWaitEvent(sA, fx.eWkvb, 0);
    hgemm<true, false><<<dim3(UPDIM / 128, S_LEN / 128), 256, sizeof(HGemmSm), sA>>>(
        hkvn, hwkvb, hkvup, S_LEN, UPDIM, KV_LORA, nullptr, nullptr);
    if (forked) cudaEventRecord(fx.eKV, sA);

    // ---- join on stream 0: attention + output projection ----
    if (forked) cudaStreamWaitEvent(0, fx.eKV, 0);
    attn_f16<<<dim3(S_LEN / BM, NHEADS), 256, sizeof(AttnSm), 0>>>(
        hq, hkvup, hkpe, hattn);
    if (forked) cudaStreamWaitEvent(0, fx.eWo, 0);
    hgemm<false, false><<<dim3(ODIM / 128, S_LEN / 128), 256, sizeof(HGemmSm), 0>>>(
        hattn, hwo, out, S_LEN, ODIM, DIM_IN, nullptr, nullptr);
}

// round 15
// speedup vs baseline: 1.0192x; 1.0192x over previous
#include <cuda_runtime.h>
#include <cuda_fp16.h>
#include <cstdint>

// ---------------- problem constants ----------------
#define S_LEN   4096
#define NHEADS  16
#define DQK     192
#define DNOPE   128
#define DROPE   64
#define DV      128
#define DIM_IN  2048
#define KV_LORA 512
#define KV_TOT  576
#define QDIM    (NHEADS*DQK)         // 3072
#define UPDIM   (NHEADS*(DNOPE+DV))  // 4096
#define ODIM    (NHEADS*DV)          // 2048
#define SOFTMAX_SCALE 0.13522975134194065f
#define SCALE_LOG2E 0.19510458386472476f

// ---------------- half scratch (device globals) ----------------
__device__ __half g_hx   [(size_t)S_LEN*DIM_IN];
__device__ __half g_hwq  [(size_t)DIM_IN*QDIM];
__device__ __half g_hwkva[(size_t)DIM_IN*KV_TOT];
__device__ __half g_hwkvb[(size_t)KV_LORA*UPDIM];
__device__ __half g_hwo  [(size_t)ODIM*DIM_IN];
__device__ __half g_hq   [(size_t)S_LEN*QDIM];
__device__ __half g_hkv  [(size_t)S_LEN*KV_TOT];
__device__ __half g_hkvn [(size_t)S_LEN*KV_LORA];
__device__ __half g_hkpe [(size_t)S_LEN*DROPE];
__device__ __half g_hkvup[(size_t)S_LEN*UPDIM];
__device__ __half g_hattn[(size_t)S_LEN*ODIM];

// ---------------- helpers ----------------
__device__ __forceinline__ uint32_t sm_u32(const void* p) {
    return (uint32_t)__cvta_generic_to_shared(p);
}
__device__ __forceinline__ void cp16(void* dst, const void* src) {
    asm volatile("cp.async.ca.shared.global [%0], [%1], 16;"
                 :: "r"(sm_u32(dst)), "l"(src));
}
__device__ __forceinline__ void cp_commit() { asm volatile("cp.async.commit_group;"); }
template<int N> __device__ __forceinline__ void cp_wait() {
    asm volatile("cp.async.wait_group %0;" :: "n"(N));
}
__device__ __forceinline__ void ldsm4(uint32_t* r, uint32_t a) {
    asm volatile("ldmatrix.sync.aligned.m8n8.x4.shared.b16 {%0,%1,%2,%3}, [%4];"
        : "=r"(r[0]), "=r"(r[1]), "=r"(r[2]), "=r"(r[3]) : "r"(a));
}
__device__ __forceinline__ void ldsm4t(uint32_t* r, uint32_t a) {
    asm volatile("ldmatrix.sync.aligned.m8n8.x4.trans.shared.b16 {%0,%1,%2,%3}, [%4];"
        : "=r"(r[0]), "=r"(r[1]), "=r"(r[2]), "=r"(r[3]) : "r"(a));
}
__device__ __forceinline__ void mma_f16(float* d, const uint32_t* a, const uint32_t* b) {
    asm volatile("mma.sync.aligned.m16n8k16.row.col.f32.f16.f16.f32 "
        "{%0,%1,%2,%3}, {%4,%5,%6,%7}, {%8,%9}, {%0,%1,%2,%3};\n"
        : "+f"(d[0]), "+f"(d[1]), "+f"(d[2]), "+f"(d[3])
        : "r"(a[0]), "r"(a[1]), "r"(a[2]), "r"(a[3]), "r"(b[0]), "r"(b[1]));
}
__device__ __forceinline__ uint32_t h2u(__half2 h) {
    return *reinterpret_cast<uint32_t*>(&h);
}
__device__ __forceinline__ float ex2(float x) {
    float y;
    asm("ex2.approx.ftz.f32 %0, %1;" : "=f"(y) : "f"(x));
    return y;
}

// ---------------- fp32 -> fp16 convert ----------------
__global__ void f2h_kernel(const float* __restrict__ in, __half* __restrict__ out, int n) {
    int i = (blockIdx.x * blockDim.x + threadIdx.x) * 4;
    if (i >= n) return;
    float4 v = *reinterpret_cast<const float4*>(&in[i]);
    __half2 a = __floats2half2_rn(v.x, v.y);
    __half2 b = __floats2half2_rn(v.z, v.w);
    uint2 p;
    p.x = *reinterpret_cast<uint32_t*>(&a);
    p.y = *reinterpret_cast<uint32_t*>(&b);
    *reinterpret_cast<uint2*>(&out[i]) = p;
}

// ---------------- HGEMM: 128x128 tile, 8 warps (4M x 2N) of 32x64 ----------------
#define GAP 40
#define GBP 136
struct HGemmSm {
    __half As[4][128][GAP];
    __half Bs[4][32][GBP];
};

template<bool HALF_OUT, bool DO_ROPE>
__global__ __launch_bounds__(256, 2) void hgemm(
    const __half* __restrict__ A, const __half* __restrict__ B,
    void* __restrict__ Cout, int M, int N, int K,
    const float* __restrict__ FC, const float* __restrict__ FS)
{
    extern __shared__ char smraw[];
    HGemmSm& sm = *reinterpret_cast<HGemmSm*>(smraw);
    const int tid = threadIdx.x, lane = tid & 31, warp = tid >> 5;
    const int wm = warp & 3, wn = warp >> 2;
    const int g = lane >> 2, tig = lane & 3;
    const int m0 = blockIdx.y * 128, n0 = blockIdx.x * 128;

    float acc[2][8][4];
    #pragma unroll
    for (int i = 0; i < 2; i++)
        #pragma unroll
        for (int j = 0; j < 8; j++)
            #pragma unroll
            for (int k = 0; k < 4; k++) acc[i][j][k] = 0.f;

    auto load = [&](int t, int st) {
        const int k0 = t * 32;
        #pragma unroll
        for (int r = 0; r < 2; r++) {
            int c = tid + r * 256;
            int row = c >> 2, kc = (c & 3) * 8;
            cp16(&sm.As[st][row][kc], &A[(size_t)(m0 + row) * K + k0 + kc]);
        }
        #pragma unroll
        for (int r = 0; r < 2; r++) {
            int c = tid + r * 256;
            int kr = c >> 4, nc = (c & 15) * 8;
            int col = n0 + nc;
            if (col < N)
                cp16(&sm.Bs[st][kr][nc], &B[(size_t)(k0 + kr) * N + col]);
            else {
                uint4 z = make_uint4(0, 0, 0, 0);
                *reinterpret_cast<uint4*>(&sm.Bs[st][kr][nc]) = z;
            }
        }
        cp_commit();
    };

    const int nt = K / 32;
    load(0, 0); load(1, 1); load(2, 2);

    for (int t = 0; t < nt; t++) {
        cp_wait<2>();
        __syncthreads();
        if (t + 3 < nt) load(t + 3, (t + 3) & 3);
        else            cp_commit();
        const int st = t & 3;

        #pragma unroll
        for (int ks = 0; ks < 32; ks += 16) {
            uint32_t af[2][4];
            #pragma unroll
            for (int mf = 0; mf < 2; mf++) {
                int row = wm * 32 + mf * 16 + (lane & 7) + ((lane >> 3) & 1) * 8;
                int col = ks + (lane >> 4) * 8;
                ldsm4(af[mf], sm_u32(&sm.As[st][row][col]));
            }
            #pragma unroll
            for (int np = 0; np < 4; np++) {
                uint32_t bb[4];
                int row = ks + (lane & 7) + ((lane >> 3) & 1) * 8;
                int col = wn * 64 + np * 16 + ((lane >> 4) & 1) * 8;
                ldsm4t(bb, sm_u32(&sm.Bs[st][row][col]));
                int nf = np * 2;
                mma_f16(acc[0][nf],     af[0], bb);
                mma_f16(acc[1][nf],     af[1], bb);
                mma_f16(acc[0][nf + 1], af[0], bb + 2);
                mma_f16(acc[1][nf + 1], af[1], bb + 2);
            }
        }
    }

    #pragma unroll
    for (int mf = 0; mf < 2; mf++) {
        #pragma unroll
        for (int nf = 0; nf < 8; nf++) {
            int r = m0 + wm * 32 + mf * 16 + g;
            int c = n0 + wn * 64 + nf * 8 + tig * 2;
            if (c < N) {
                float a0 = acc[mf][nf][0], a1 = acc[mf][nf][1];
                float a2 = acc[mf][nf][2], a3 = acc[mf][nf][3];
                if (DO_ROPE) {
                    int d = c % DQK;
                    if (d >= DNOPE) {
                        int p = (d - DNOPE) >> 1;
                        float c0 = FC[r * 32 + p],       s0 = FS[r * 32 + p];
                        float c1 = FC[(r + 8) * 32 + p], s1 = FS[(r + 8) * 32 + p];
                        float t0 = a0 * c0 - a1 * s0, t1 = a0 * s0 + a1 * c0;
                        float t2 = a2 * c1 - a3 * s1, t3 = a2 * s1 + a3 * c1;
                        a0 = t0; a1 = t1; a2 = t2; a3 = t3;
                    }
                }
                if (HALF_OUT) {
                    __half* C = (__half*)Cout;
                    *reinterpret_cast<__half2*>(&C[(size_t)r * N + c]) =
                        __floats2half2_rn(a0, a1);
                    *reinterpret_cast<__half2*>(&C[(size_t)(r + 8) * N + c]) =
                        __floats2half2_rn(a2, a3);
                } else {
                    float* C = (float*)Cout;
                    *reinterpret_cast<float2*>(&C[(size_t)r * N + c]) = make_float2(a0, a1);
                    *reinterpret_cast<float2*>(&C[(size_t)(r + 8) * N + c]) = make_float2(a2, a3);
                }
            }
        }
    }
}

// ---------------- rmsnorm + rope(k_pe) (half io) ----------------
__global__ void kvnorm_kernel(const __half* __restrict__ KV,
                              const float* __restrict__ W,
                              const float* __restrict__ C,
                              const float* __restrict__ Sn,
                              __half* __restrict__ KVN,
                              __half* __restrict__ KPE)
{
    int s = blockIdx.x;
    int tid = threadIdx.x;
    const __half* row = KV + (size_t)s * KV_TOT;

    float ss = 0.f;
    for (int i = tid; i < KV_LORA; i += 256) {
        float v = __half2float(row[i]); ss += v * v;
    }
    __shared__ float red[256];
    red[tid] = ss;
    __syncthreads();
    for (int off = 128; off > 0; off >>= 1) {
        if (tid < off) red[tid] += red[tid + off];
        __syncthreads();
    }
    __shared__ float rinv;
    if (tid == 0) rinv = rsqrtf(red[0] * (1.0f / KV_LORA) + 1e-6f);
    __syncthreads();
    float r = rinv;
    for (int i = tid; i < KV_LORA; i += 256)
        KVN[(size_t)s * KV_LORA + i] = __float2half_rn(__half2float(row[i]) * r * W[i]);

    if (tid < 32) {
        int p = tid;
        float xr = __half2float(row[KV_LORA + 2 * p]);
        float xi = __half2float(row[KV_LORA + 2 * p + 1]);
        float c = C[s * 32 + p], sn = Sn[s * 32 + p];
        *reinterpret_cast<__half2*>(&KPE[(size_t)s * DROPE + 2 * p]) =
            __floats2half2_rn(xr * c - xi * sn, xr * sn + xi * c);
    }
}

// ---------------- flash attention v8: R13 body + 3-stage KV ring ----------------
#define BM 128
#define BN 64
#define QKP 200
#define VSP 136
#define NST 3

struct AttnSm {
    __half Qt[BM][QKP];         // 51200 B
    __half Kt[NST][BN][QKP];    // 76800 B
    __half Vs[NST][BN][VSP];    // 52224 B  -> 180224 B
};

__global__ __launch_bounds__(256, 1) void attn_f16(
    const __half* __restrict__ Q,
    const __half* __restrict__ KVUP,
    const __half* __restrict__ KPE,
    __half* __restrict__ O)
{
    extern __shared__ char smraw[];
    AttnSm& sm = *reinterpret_cast<AttnSm*>(smraw);
    const int tid = threadIdx.x, lane = tid & 31, warp = tid >> 5;
    const int g = lane >> 2, tig = lane & 3;
    const int qb = (int)gridDim.x - 1 - (int)blockIdx.x;
    const int h  = blockIdx.y;
    const int qs0 = qb * BM;

    auto load_kv = [&](int kb, int buf) {
        const int ks0 = kb * BN;
        #pragma unroll
        for (int r = 0; r < 6; r++) {
            int c = tid + r * 256;
            int n = c / 24, dc = c % 24;
            if (dc < 16)
                cp16(&sm.Kt[buf][n][dc * 8],
                     &KVUP[(size_t)(ks0 + n) * UPDIM + h * 256 + dc * 8]);
            else
                cp16(&sm.Kt[buf][n][128 + (dc - 16) * 8],
                     &KPE[(size_t)(ks0 + n) * DROPE + (dc - 16) * 8]);
        }
        #pragma unroll
        for (int r = 0; r < 4; r++) {
            int c = tid + r * 256;
            int n = c >> 4, dc = c & 15;
            cp16(&sm.Vs[buf][n][dc * 8],
                 &KVUP[(size_t)(ks0 + n) * UPDIM + h * 256 + 128 + dc * 8]);
        }
        cp_commit();
    };

    const int nkb = 2 * qb + 2;

    // stage Q tile (own group) + first two KV blocks
    for (int c = tid; c < BM * 24; c += 256) {
        int m = c / 24, dc = c % 24;
        cp16(&sm.Qt[m][dc * 8], &Q[(size_t)(qs0 + m) * QDIM + h * DQK + dc * 8]);
    }
    cp_commit();
    load_kv(0, 0);
    load_kv(1, 1);                 // nkb >= 2 always
    cp_wait<1>();                  // Q + block0 ready; block1 may be in flight
    __syncthreads();

    // hoist Q fragments to registers
    uint32_t qf[DQK / 16][4];
    #pragma unroll
    for (int ks = 0; ks < DQK / 16; ks++) {
        int row = warp * 16 + (lane & 7) + ((lane >> 3) & 1) * 8;
        int col = ks * 16 + (lane >> 4) * 8;
        ldsm4(qf[ks], sm_u32(&sm.Qt[row][col]));
    }

    const int rl = warp * 16 + g;
    const int rg0 = qs0 + rl, rg1 = rg0 + 8;
    float r_m0 = -3.0e38f, r_m1 = -3.0e38f;
    float r_l0 = 0.f, r_l1 = 0.f;

    float o_acc[16][4];
    #pragma unroll
    for (int j = 0; j < 16; j++)
        #pragma unroll
        for (int k = 0; k < 4; k++) o_acc[j][k] = 0.f;

    int buf = 0;
    for (int kb = 0; kb < nkb; kb++) {
        const int ks0 = kb * BN;
        if (kb > 0) {
            cp_wait<1>();          // block kb ready (next load may stay in flight)
            __syncthreads();       // also: everyone done reading buffer (kb-1)%3
        }
        if (kb + 2 < nkb) load_kv(kb + 2, (buf + 2) % NST);
        else              cp_commit();   // keep group count uniform

        // ---- GEMM1: pipelined K fragments ----
        float s_acc[8][4];
        #pragma unroll
        for (int j = 0; j < 8; j++)
            #pragma unroll
            for (int k = 0; k < 4; k++) s_acc[j][k] = 0.f;

        auto ldK = [&](int ks, uint32_t* dst) {
            #pragma unroll
            for (int np = 0; np < 4; np++) {
                int row = np * 16 + ((lane >> 4) & 1) * 8 + (lane & 7);
                int col = ks * 16 + ((lane >> 3) & 1) * 8;
                ldsm4(dst + np * 4, sm_u32(&sm.Kt[buf][row][col]));
            }
        };
        {
            uint32_t kf[2][16];
            ldK(0, kf[0]);
            #pragma unroll
            for (int ks = 0; ks < DQK / 16; ks++) {
                const int cur = ks & 1;
                if (ks + 1 < DQK / 16) ldK(ks + 1, kf[cur ^ 1]);
                #pragma unroll
                for (int np = 0; np < 4; np++) {
                    mma_f16(s_acc[np * 2],     qf[ks], kf[cur] + np * 4);
                    mma_f16(s_acc[np * 2 + 1], qf[ks], kf[cur] + np * 4 + 2);
                }
            }
        }

        // ---- V prefetch (half-chunk 0) ----
        auto ldV = [&](int hc, uint32_t* dst) {
            int ks = hc >> 1, nh = hc & 1;
            #pragma unroll
            for (int j = 0; j < 4; j++) {
                int np = nh * 4 + j;
                int row = ks * 16 + (lane & 7) + ((lane >> 3) & 1) * 8;
                int col = np * 16 + ((lane >> 4) & 1) * 8;
                ldsm4t(dst + j * 4, sm_u32(&sm.Vs[buf][row][col]));
            }
        };
        uint32_t vf[2][16];
        ldV(0, vf[0]);

        // ---- scale to log2 domain; mask only in the 2 diagonal blocks ----
        #pragma unroll
        for (int nf = 0; nf < 8; nf++) {
            s_acc[nf][0] *= SCALE_LOG2E;
            s_acc[nf][1] *= SCALE_LOG2E;
            s_acc[nf][2] *= SCALE_LOG2E;
            s_acc[nf][3] *= SCALE_LOG2E;
        }
        if (kb >= nkb - 2) {
            #pragma unroll
            for (int nf = 0; nf < 8; nf++) {
                int cg = ks0 + nf * 8 + tig * 2;
                if (cg     > rg0) s_acc[nf][0] = -1.0e30f;
                if (cg + 1 > rg0) s_acc[nf][1] = -1.0e30f;
                if (cg     > rg1) s_acc[nf][2] = -1.0e30f;
                if (cg + 1 > rg1) s_acc[nf][3] = -1.0e30f;
            }
        }

        // ---- warp-local online softmax (log2 domain) ----
        float mx0 = -3.0e38f, mx1 = -3.0e38f;
        #pragma unroll
        for (int nf = 0; nf < 8; nf++) {
            mx0 = fmaxf(mx0, fmaxf(s_acc[nf][0], s_acc[nf][1]));
            mx1 = fmaxf(mx1, fmaxf(s_acc[nf][2], s_acc[nf][3]));
        }
        mx0 = fmaxf(mx0, __shfl_xor_sync(0xffffffffu, mx0, 1));
        mx0 = fmaxf(mx0, __shfl_xor_sync(0xffffffffu, mx0, 2));
        mx1 = fmaxf(mx1, __shfl_xor_sync(0xffffffffu, mx1, 1));
        mx1 = fmaxf(mx1, __shfl_xor_sync(0xffffffffu, mx1, 2));

        float nm0 = fmaxf(r_m0, mx0), nm1 = fmaxf(r_m1, mx1);
        float a0 = ex2(r_m0 - nm0), a1 = ex2(r_m1 - nm1);
        r_m0 = nm0; r_m1 = nm1;

        uint32_t pa[4][4];
        float sum0 = 0.f, sum1 = 0.f;
        #pragma unroll
        for (int nf = 0; nf < 8; nf++) {
            float p0 = ex2(s_acc[nf][0] - nm0);
            float p1 = ex2(s_acc[nf][1] - nm0);
            float p2 = ex2(s_acc[nf][2] - nm1);
            float p3 = ex2(s_acc[nf][3] - nm1);
            sum0 += p0 + p1; sum1 += p2 + p3;
            pa[nf >> 1][(nf & 1) * 2 + 0] = h2u(__floats2half2_rn(p0, p1));
            pa[nf >> 1][(nf & 1) * 2 + 1] = h2u(__floats2half2_rn(p2, p3));
        }
        sum0 += __shfl_xor_sync(0xffffffffu, sum0, 1);
        sum0 += __shfl_xor_sync(0xffffffffu, sum0, 2);
        sum1 += __shfl_xor_sync(0xffffffffu, sum1, 1);
        sum1 += __shfl_xor_sync(0xffffffffu, sum1, 2);
        r_l0 = r_l0 * a0 + sum0;
        r_l1 = r_l1 * a1 + sum1;

        // ---- GEMM2: O = alpha*O + P V, pipelined V half-chunks ----
        #pragma unroll
        for (int nf = 0; nf < 16; nf++) {
            o_acc[nf][0] *= a0; o_acc[nf][1] *= a0;
            o_acc[nf][2] *= a1; o_acc[nf][3] *= a1;
        }
        #pragma unroll
        for (int hc = 0; hc < 8; hc++) {
            const int cur = hc & 1;
            if (hc + 1 < 8) ldV(hc + 1, vf[cur ^ 1]);
            const int ks = hc >> 1, nh = hc & 1;
            #pragma unroll
            for (int j = 0; j < 4; j++) {
                int np = nh * 4 + j;
                mma_f16(o_acc[np * 2],     pa[ks], vf[cur] + j * 4);
                mma_f16(o_acc[np * 2 + 1], pa[ks], vf[cur] + j * 4 + 2);
            }
        }

        buf = (buf + 1) % NST;
    }

    float inv0 = 1.0f / r_l0, inv1 = 1.0f / r_l1;
    #pragma unroll
    for (int nf = 0; nf < 16; nf++) {
        int col = h * DV + nf * 8 + tig * 2;
        *reinterpret_cast<__half2*>(&O[(size_t)rg0 * ODIM + col]) =
            __floats2half2_rn(o_acc[nf][0] * inv0, o_acc[nf][1] * inv0);
        *reinterpret_cast<__half2*>(&O[(size_t)rg1 * ODIM + col]) =
            __floats2half2_rn(o_acc[nf][2] * inv1, o_acc[nf][3] * inv1);
    }
}

// ---------------- persistent stream/event holder ----------------
struct ForkCtx {
    cudaStream_t sA = 0, sB = 0;
    cudaEvent_t  eFork = 0, eX = 0, eWkvb = 0, eWo = 0, eKV = 0;
    bool ok = false;
    ForkCtx() {
        ok = (cudaStreamCreateWithFlags(&sA, cudaStreamNonBlocking) == cudaSuccess) &&
             (cudaStreamCreateWithFlags(&sB, cudaStreamNonBlocking) == cudaSuccess) &&
             (cudaEventCreateWithFlags(&eFork, cudaEventDisableTiming) == cudaSuccess) &&
             (cudaEventCreateWithFlags(&eX,    cudaEventDisableTiming) == cudaSuccess) &&
             (cudaEventCreateWithFlags(&eWkvb, cudaEventDisableTiming) == cudaSuccess) &&
             (cudaEventCreateWithFlags(&eWo,   cudaEventDisableTiming) == cudaSuccess) &&
             (cudaEventCreateWithFlags(&eKV,   cudaEventDisableTiming) == cudaSuccess);
    }
};

// ---------------- launcher: multi-stream fork/join inside graph capture ----------------
extern "C" void kernel_launch(void* const* d_in, const int* in_sizes, int n_in,
                              void* d_out, int out_size)
{
    (void)in_sizes; (void)n_in; (void)out_size;
    const float* x    = (const float*)d_in[0];
    const float* fc   = (const float*)d_in[1];
    const float* fs   = (const float*)d_in[2];
    const float* wq   = (const float*)d_in[4];
    const float* wkva = (const float*)d_in[5];
    const float* kvw  = (const float*)d_in[6];
    const float* wkvb = (const float*)d_in[7];
    const float* wo   = (const float*)d_in[8];
    float* out = (float*)d_out;

    __half *hx, *hwq, *hwkva, *hwkvb, *hwo, *hq, *hkv, *hkvn, *hkpe, *hkvup, *hattn;
    cudaGetSymbolAddress((void**)&hx,    g_hx);
    cudaGetSymbolAddress((void**)&hwq,   g_hwq);
    cudaGetSymbolAddress((void**)&hwkva, g_hwkva);
    cudaGetSymbolAddress((void**)&hwkvb, g_hwkvb);
    cudaGetSymbolAddress((void**)&hwo,   g_hwo);
    cudaGetSymbolAddress((void**)&hq,    g_hq);
    cudaGetSymbolAddress((void**)&hkv,   g_hkv);
    cudaGetSymbolAddress((void**)&hkvn,  g_hkvn);
    cudaGetSymbolAddress((void**)&hkpe,  g_hkpe);
    cudaGetSymbolAddress((void**)&hkvup, g_hkvup);
    cudaGetSymbolAddress((void**)&hattn, g_hattn);

    cudaFuncSetAttribute((const void*)hgemm<true, false>,
        cudaFuncAttributeMaxDynamicSharedMemorySize, (int)sizeof(HGemmSm));
    cudaFuncSetAttribute((const void*)hgemm<true, true>,
        cudaFuncAttributeMaxDynamicSharedMemorySize, (int)sizeof(HGemmSm));
    cudaFuncSetAttribute((const void*)hgemm<false, false>,
        cudaFuncAttributeMaxDynamicSharedMemorySize, (int)sizeof(HGemmSm));
    cudaFuncSetAttribute((const void*)attn_f16,
        cudaFuncAttributeMaxDynamicSharedMemorySize, (int)sizeof(AttnSm));

    static ForkCtx fx;
    const bool forked = fx.ok;
    cudaStream_t sA = forked ? fx.sA : 0;
    cudaStream_t sB = forked ? fx.sB : 0;

    if (forked) {
        cudaEventRecord(fx.eFork, 0);
        cudaStreamWaitEvent(sA, fx.eFork, 0);
        cudaStreamWaitEvent(sB, fx.eFork, 0);
    }

    // ---- stream 0: x convert + Q path (rope fused into q projection) ----
    f2h_kernel<<<(S_LEN*DIM_IN) / 1024, 256, 0, 0>>>(x, hx, S_LEN*DIM_IN);
    if (forked) cudaEventRecord(fx.eX, 0);
    f2h_kernel<<<(DIM_IN*QDIM) / 1024, 256, 0, 0>>>(wq, hwq, DIM_IN*QDIM);
    hgemm<true, true><<<dim3(QDIM / 128, S_LEN / 128), 256, sizeof(HGemmSm), 0>>>(
        hx, hwq, hq, S_LEN, QDIM, DIM_IN, fc, fs);

    // ---- stream B: independent weight conversions ----
    f2h_kernel<<<(KV_LORA*UPDIM) / 1024, 256, 0, sB>>>(wkvb, hwkvb, KV_LORA*UPDIM);
    if (forked) cudaEventRecord(fx.eWkvb, sB);
    f2h_kernel<<<(ODIM*DIM_IN) / 1024, 256, 0, sB>>>(wo, hwo, ODIM*DIM_IN);
    if (forked) cudaEventRecord(fx.eWo, sB);

    // ---- stream A: KV path ----
    f2h_kernel<<<(DIM_IN*KV_TOT) / 1024, 256, 0, sA>>>(wkva, hwkva, DIM_IN*KV_TOT);
    if (forked) cudaStreamWaitEvent(sA, fx.eX, 0);
    hgemm<true, false><<<dim3((KV_TOT + 127) / 128, S_LEN / 128), 256, sizeof(HGemmSm), sA>>>(
        hx, hwkva, hkv, S_LEN, KV_TOT, DIM_IN, nullptr, nullptr);
    kvnorm_kernel<<<S_LEN, 256, 0, sA>>>(hkv, kvw, fc, fs, hkvn, hkpe);
    if (forked) cudaStreamWaitEvent(sA, fx.eWkvb, 0);
    hgemm<true, false><<<dim3(UPDIM / 128, S_LEN / 128), 256, sizeof(HGemmSm), sA>>>(
        hkvn, hwkvb, hkvup, S_LEN, UPDIM, KV_LORA, nullptr, nullptr);
    if (forked) cudaEventRecord(fx.eKV, sA);

    // ---- join on stream 0: attention + output projection ----
    if (forked) cudaStreamWaitEvent(0, fx.eKV, 0);
    attn_f16<<<dim3(S_LEN / BM, NHEADS), 256, sizeof(AttnSm), 0>>>(
        hq, hkvup, hkpe, hattn);
    if (forked) cudaStreamWaitEvent(0, fx.eWo, 0);
    hgemm<false, false><<<dim3(ODIM / 128, S_LEN / 128), 256, sizeof(HGemmSm), 0>>>(
        hattn, hwo, out, S_LEN, ODIM, DIM_IN, nullptr, nullptr);
}

// round 16
// speedup vs baseline: 1.1191x; 1.0981x over previous
#include <cuda_runtime.h>
#include <cuda_fp16.h>
#include <cstdint>

// ---------------- problem constants ----------------
#define S_LEN   4096
#define NHEADS  16
#define DQK     192
#define DNOPE   128
#define DROPE   64
#define DV      128
#define DIM_IN  2048
#define KV_LORA 512
#define KV_TOT  576
#define QDIM    (NHEADS*DQK)         // 3072
#define UPDIM   (NHEADS*(DNOPE+DV))  // 4096
#define ODIM    (NHEADS*DV)          // 2048
#define SOFTMAX_SCALE 0.13522975134194065f
#define SCALE_LOG2E 0.19510458386472476f

// ---------------- half scratch (device globals) ----------------
__device__ __half g_hx   [(size_t)S_LEN*DIM_IN];
__device__ __half g_hwq  [(size_t)DIM_IN*QDIM];
__device__ __half g_hwkva[(size_t)DIM_IN*KV_TOT];
__device__ __half g_hwkvb[(size_t)KV_LORA*UPDIM];
__device__ __half g_hwo  [(size_t)ODIM*DIM_IN];
__device__ __half g_hq   [(size_t)S_LEN*QDIM];
__device__ __half g_hkv  [(size_t)S_LEN*KV_TOT];
__device__ __half g_hkvn [(size_t)S_LEN*KV_LORA];
__device__ __half g_hkpe [(size_t)S_LEN*DROPE];
__device__ __half g_hkvup[(size_t)S_LEN*UPDIM];
__device__ __half g_hattn[(size_t)S_LEN*ODIM];

// ---------------- helpers ----------------
__device__ __forceinline__ uint32_t sm_u32(const void* p) {
    return (uint32_t)__cvta_generic_to_shared(p);
}
__device__ __forceinline__ void cp16(void* dst, const void* src) {
    asm volatile("cp.async.ca.shared.global [%0], [%1], 16;"
                 :: "r"(sm_u32(dst)), "l"(src));
}
__device__ __forceinline__ void cp_commit() { asm volatile("cp.async.commit_group;"); }
template<int N> __device__ __forceinline__ void cp_wait() {
    asm volatile("cp.async.wait_group %0;" :: "n"(N));
}
__device__ __forceinline__ void ldsm4(uint32_t* r, uint32_t a) {
    asm volatile("ldmatrix.sync.aligned.m8n8.x4.shared.b16 {%0,%1,%2,%3}, [%4];"
        : "=r"(r[0]), "=r"(r[1]), "=r"(r[2]), "=r"(r[3]) : "r"(a));
}
__device__ __forceinline__ void ldsm4t(uint32_t* r, uint32_t a) {
    asm volatile("ldmatrix.sync.aligned.m8n8.x4.trans.shared.b16 {%0,%1,%2,%3}, [%4];"
        : "=r"(r[0]), "=r"(r[1]), "=r"(r[2]), "=r"(r[3]) : "r"(a));
}
__device__ __forceinline__ void mma_f16(float* d, const uint32_t* a, const uint32_t* b) {
    asm volatile("mma.sync.aligned.m16n8k16.row.col.f32.f16.f16.f32 "
        "{%0,%1,%2,%3}, {%4,%5,%6,%7}, {%8,%9}, {%0,%1,%2,%3};\n"
        : "+f"(d[0]), "+f"(d[1]), "+f"(d[2]), "+f"(d[3])
        : "r"(a[0]), "r"(a[1]), "r"(a[2]), "r"(a[3]), "r"(b[0]), "r"(b[1]));
}
__device__ __forceinline__ uint32_t h2u(__half2 h) {
    return *reinterpret_cast<uint32_t*>(&h);
}
__device__ __forceinline__ float ex2(float x) {
    float y;
    asm("ex2.approx.ftz.f32 %0, %1;" : "=f"(y) : "f"(x));
    return y;
}

// ---------------- fp32 -> fp16 convert ----------------
__global__ void f2h_kernel(const float* __restrict__ in, __half* __restrict__ out, int n) {
    int i = (blockIdx.x * blockDim.x + threadIdx.x) * 4;
    if (i >= n) return;
    float4 v = *reinterpret_cast<const float4*>(&in[i]);
    __half2 a = __floats2half2_rn(v.x, v.y);
    __half2 b = __floats2half2_rn(v.z, v.w);
    uint2 p;
    p.x = *reinterpret_cast<uint32_t*>(&a);
    p.y = *reinterpret_cast<uint32_t*>(&b);
    *reinterpret_cast<uint2*>(&out[i]) = p;
}

// ---------------- HGEMM: 128x128 tile, 8 warps (4M x 2N) of 32x64 ----------------
#define GAP 40
#define GBP 136
struct HGemmSm {
    __half As[4][128][GAP];
    __half Bs[4][32][GBP];
};

template<bool HALF_OUT, bool DO_ROPE>
__global__ __launch_bounds__(256, 2) void hgemm(
    const __half* __restrict__ A, const __half* __restrict__ B,
    void* __restrict__ Cout, int M, int N, int K,
    const float* __restrict__ FC, const float* __restrict__ FS,
    int m0_base)
{
    extern __shared__ char smraw[];
    HGemmSm& sm = *reinterpret_cast<HGemmSm*>(smraw);
    const int tid = threadIdx.x, lane = tid & 31, warp = tid >> 5;
    const int wm = warp & 3, wn = warp >> 2;
    const int g = lane >> 2, tig = lane & 3;
    const int m0 = m0_base + blockIdx.y * 128, n0 = blockIdx.x * 128;

    float acc[2][8][4];
    #pragma unroll
    for (int i = 0; i < 2; i++)
        #pragma unroll
        for (int j = 0; j < 8; j++)
            #pragma unroll
            for (int k = 0; k < 4; k++) acc[i][j][k] = 0.f;

    auto load = [&](int t, int st) {
        const int k0 = t * 32;
        #pragma unroll
        for (int r = 0; r < 2; r++) {
            int c = tid + r * 256;
            int row = c >> 2, kc = (c & 3) * 8;
            cp16(&sm.As[st][row][kc], &A[(size_t)(m0 + row) * K + k0 + kc]);
        }
        #pragma unroll
        for (int r = 0; r < 2; r++) {
            int c = tid + r * 256;
            int kr = c >> 4, nc = (c & 15) * 8;
            int col = n0 + nc;
            if (col < N)
                cp16(&sm.Bs[st][kr][nc], &B[(size_t)(k0 + kr) * N + col]);
            else {
                uint4 z = make_uint4(0, 0, 0, 0);
                *reinterpret_cast<uint4*>(&sm.Bs[st][kr][nc]) = z;
            }
        }
        cp_commit();
    };

    const int nt = K / 32;
    load(0, 0); load(1, 1); load(2, 2);

    for (int t = 0; t < nt; t++) {
        cp_wait<2>();
        __syncthreads();
        if (t + 3 < nt) load(t + 3, (t + 3) & 3);
        else            cp_commit();
        const int st = t & 3;

        #pragma unroll
        for (int ks = 0; ks < 32; ks += 16) {
            uint32_t af[2][4];
            #pragma unroll
            for (int mf = 0; mf < 2; mf++) {
                int row = wm * 32 + mf * 16 + (lane & 7) + ((lane >> 3) & 1) * 8;
                int col = ks + (lane >> 4) * 8;
                ldsm4(af[mf], sm_u32(&sm.As[st][row][col]));
            }
            #pragma unroll
            for (int np = 0; np < 4; np++) {
                uint32_t bb[4];
                int row = ks + (lane & 7) + ((lane >> 3) & 1) * 8;
                int col = wn * 64 + np * 16 + ((lane >> 4) & 1) * 8;
                ldsm4t(bb, sm_u32(&sm.Bs[st][row][col]));
                int nf = np * 2;
                mma_f16(acc[0][nf],     af[0], bb);
                mma_f16(acc[1][nf],     af[1], bb);
                mma_f16(acc[0][nf + 1], af[0], bb + 2);
                mma_f16(acc[1][nf + 1], af[1], bb + 2);
            }
        }
    }

    #pragma unroll
    for (int mf = 0; mf < 2; mf++) {
        #pragma unroll
        for (int nf = 0; nf < 8; nf++) {
            int r = m0 + wm * 32 + mf * 16 + g;
            int c = n0 + wn * 64 + nf * 8 + tig * 2;
            if (c < N) {
                float a0 = acc[mf][nf][0], a1 = acc[mf][nf][1];
                float a2 = acc[mf][nf][2], a3 = acc[mf][nf][3];
                if (DO_ROPE) {
                    int d = c % DQK;
                    if (d >= DNOPE) {
                        int p = (d - DNOPE) >> 1;
                        float c0 = FC[r * 32 + p],       s0 = FS[r * 32 + p];
                        float c1 = FC[(r + 8) * 32 + p], s1 = FS[(r + 8) * 32 + p];
                        float t0 = a0 * c0 - a1 * s0, t1 = a0 * s0 + a1 * c0;
                        float t2 = a2 * c1 - a3 * s1, t3 = a2 * s1 + a3 * c1;
                        a0 = t0; a1 = t1; a2 = t2; a3 = t3;
                    }
                }
                if (HALF_OUT) {
                    __half* C = (__half*)Cout;
                    *reinterpret_cast<__half2*>(&C[(size_t)r * N + c]) =
                        __floats2half2_rn(a0, a1);
                    *reinterpret_cast<__half2*>(&C[(size_t)(r + 8) * N + c]) =
                        __floats2half2_rn(a2, a3);
                } else {
                    float* C = (float*)Cout;
                    *reinterpret_cast<float2*>(&C[(size_t)r * N + c]) = make_float2(a0, a1);
                    *reinterpret_cast<float2*>(&C[(size_t)(r + 8) * N + c]) = make_float2(a2, a3);
                }
            }
        }
    }
}

// ---------------- rmsnorm + rope(k_pe) (half io) ----------------
__global__ void kvnorm_kernel(const __half* __restrict__ KV,
                              const float* __restrict__ W,
                              const float* __restrict__ C,
                              const float* __restrict__ Sn,
                              __half* __restrict__ KVN,
                              __half* __restrict__ KPE)
{
    int s = blockIdx.x;
    int tid = threadIdx.x;
    const __half* row = KV + (size_t)s * KV_TOT;

    float ss = 0.f;
    for (int i = tid; i < KV_LORA; i += 256) {
        float v = __half2float(row[i]); ss += v * v;
    }
    __shared__ float red[256];
    red[tid] = ss;
    __syncthreads();
    for (int off = 128; off > 0; off >>= 1) {
        if (tid < off) red[tid] += red[tid + off];
        __syncthreads();
    }
    __shared__ float rinv;
    if (tid == 0) rinv = rsqrtf(red[0] * (1.0f / KV_LORA) + 1e-6f);
    __syncthreads();
    float r = rinv;
    for (int i = tid; i < KV_LORA; i += 256)
        KVN[(size_t)s * KV_LORA + i] = __float2half_rn(__half2float(row[i]) * r * W[i]);

    if (tid < 32) {
        int p = tid;
        float xr = __half2float(row[KV_LORA + 2 * p]);
        float xi = __half2float(row[KV_LORA + 2 * p + 1]);
        float c = C[s * 32 + p], sn = Sn[s * 32 + p];
        *reinterpret_cast<__half2*>(&KPE[(size_t)s * DROPE + 2 * p]) =
            __floats2half2_rn(xr * c - xi * sn, xr * sn + xi * c);
    }
}

// ---------------- flash attention v8 (R15 body) + qb_base for split launches ----------------
#define BM 128
#define BN 64
#define QKP 200
#define VSP 136
#define NST 3

struct AttnSm {
    __half Qt[BM][QKP];
    __half Kt[NST][BN][QKP];
    __half Vs[NST][BN][VSP];
};

__global__ __launch_bounds__(256, 1) void attn_f16(
    const __half* __restrict__ Q,
    const __half* __restrict__ KVUP,
    const __half* __restrict__ KPE,
    __half* __restrict__ O,
    int qb_base)
{
    extern __shared__ char smraw[];
    AttnSm& sm = *reinterpret_cast<AttnSm*>(smraw);
    const int tid = threadIdx.x, lane = tid & 31, warp = tid >> 5;
    const int g = lane >> 2, tig = lane & 3;
    const int qb = qb_base + (int)gridDim.x - 1 - (int)blockIdx.x;  // heavy first
    const int h  = blockIdx.y;
    const int qs0 = qb * BM;

    auto load_kv = [&](int kb, int buf) {
        const int ks0 = kb * BN;
        #pragma unroll
        for (int r = 0; r < 6; r++) {
            int c = tid + r * 256;
            int n = c / 24, dc = c % 24;
            if (dc < 16)
                cp16(&sm.Kt[buf][n][dc * 8],
                     &KVUP[(size_t)(ks0 + n) * UPDIM + h * 256 + dc * 8]);
            else
                cp16(&sm.Kt[buf][n][128 + (dc - 16) * 8],
                     &KPE[(size_t)(ks0 + n) * DROPE + (dc - 16) * 8]);
        }
        #pragma unroll
        for (int r = 0; r < 4; r++) {
            int c = tid + r * 256;
            int n = c >> 4, dc = c & 15;
            cp16(&sm.Vs[buf][n][dc * 8],
                 &KVUP[(size_t)(ks0 + n) * UPDIM + h * 256 + 128 + dc * 8]);
        }
        cp_commit();
    };

    const int nkb = 2 * qb + 2;

    for (int c = tid; c < BM * 24; c += 256) {
        int m = c / 24, dc = c % 24;
        cp16(&sm.Qt[m][dc * 8], &Q[(size_t)(qs0 + m) * QDIM + h * DQK + dc * 8]);
    }
    cp_commit();
    load_kv(0, 0);
    load_kv(1, 1);
    cp_wait<1>();
    __syncthreads();

    uint32_t qf[DQK / 16][4];
    #pragma unroll
    for (int ks = 0; ks < DQK / 16; ks++) {
        int row = warp * 16 + (lane & 7) + ((lane >> 3) & 1) * 8;
        int col = ks * 16 + (lane >> 4) * 8;
        ldsm4(qf[ks], sm_u32(&sm.Qt[row][col]));
    }

    const int rl = warp * 16 + g;
    const int rg0 = qs0 + rl, rg1 = rg0 + 8;
    float r_m0 = -3.0e38f, r_m1 = -3.0e38f;
    float r_l0 = 0.f, r_l1 = 0.f;

    float o_acc[16][4];
    #pragma unroll
    for (int j = 0; j < 16; j++)
        #pragma unroll
        for (int k = 0; k < 4; k++) o_acc[j][k] = 0.f;

    int buf = 0;
    for (int kb = 0; kb < nkb; kb++) {
        const int ks0 = kb * BN;
        if (kb > 0) {
            cp_wait<1>();
            __syncthreads();
        }
        if (kb + 2 < nkb) load_kv(kb + 2, (buf + 2) % NST);
        else              cp_commit();

        float s_acc[8][4];
        #pragma unroll
        for (int j = 0; j < 8; j++)
            #pragma unroll
            for (int k = 0; k < 4; k++) s_acc[j][k] = 0.f;

        auto ldK = [&](int ks, uint32_t* dst) {
            #pragma unroll
            for (int np = 0; np < 4; np++) {
                int row = np * 16 + ((lane >> 4) & 1) * 8 + (lane & 7);
                int col = ks * 16 + ((lane >> 3) & 1) * 8;
                ldsm4(dst + np * 4, sm_u32(&sm.Kt[buf][row][col]));
            }
        };
        {
            uint32_t kf[2][16];
            ldK(0, kf[0]);
            #pragma unroll
            for (int ks = 0; ks < DQK / 16; ks++) {
                const int cur = ks & 1;
                if (ks + 1 < DQK / 16) ldK(ks + 1, kf[cur ^ 1]);
                #pragma unroll
                for (int np = 0; np < 4; np++) {
                    mma_f16(s_acc[np * 2],     qf[ks], kf[cur] + np * 4);
                    mma_f16(s_acc[np * 2 + 1], qf[ks], kf[cur] + np * 4 + 2);
                }
            }
        }

        auto ldV = [&](int hc, uint32_t* dst) {
            int ks = hc >> 1, nh = hc & 1;
            #pragma unroll
            for (int j = 0; j < 4; j++) {
                int np = nh * 4 + j;
                int row = ks * 16 + (lane & 7) + ((lane >> 3) & 1) * 8;
                int col = np * 16 + ((lane >> 4) & 1) * 8;
                ldsm4t(dst + j * 4, sm_u32(&sm.Vs[buf][row][col]));
            }
        };
        uint32_t vf[2][16];
        ldV(0, vf[0]);

        #pragma unroll
        for (int nf = 0; nf < 8; nf++) {
            s_acc[nf][0] *= SCALE_LOG2E;
            s_acc[nf][1] *= SCALE_LOG2E;
            s_acc[nf][2] *= SCALE_LOG2E;
            s_acc[nf][3] *= SCALE_LOG2E;
        }
        if (kb >= nkb - 2) {
            #pragma unroll
            for (int nf = 0; nf < 8; nf++) {
                int cg = ks0 + nf * 8 + tig * 2;
                if (cg     > rg0) s_acc[nf][0] = -1.0e30f;
                if (cg + 1 > rg0) s_acc[nf][1] = -1.0e30f;
                if (cg     > rg1) s_acc[nf][2] = -1.0e30f;
                if (cg + 1 > rg1) s_acc[nf][3] = -1.0e30f;
            }
        }

        float mx0 = -3.0e38f, mx1 = -3.0e38f;
        #pragma unroll
        for (int nf = 0; nf < 8; nf++) {
            mx0 = fmaxf(mx0, fmaxf(s_acc[nf][0], s_acc[nf][1]));
            mx1 = fmaxf(mx1, fmaxf(s_acc[nf][2], s_acc[nf][3]));
        }
        mx0 = fmaxf(mx0, __shfl_xor_sync(0xffffffffu, mx0, 1));
        mx0 = fmaxf(mx0, __shfl_xor_sync(0xffffffffu, mx0, 2));
        mx1 = fmaxf(mx1, __shfl_xor_sync(0xffffffffu, mx1, 1));
        mx1 = fmaxf(mx1, __shfl_xor_sync(0xffffffffu, mx1, 2));

        float nm0 = fmaxf(r_m0, mx0), nm1 = fmaxf(r_m1, mx1);
        float a0 = ex2(r_m0 - nm0), a1 = ex2(r_m1 - nm1);
        r_m0 = nm0; r_m1 = nm1;

        uint32_t pa[4][4];
        float sum0 = 0.f, sum1 = 0.f;
        #pragma unroll
        for (int nf = 0; nf < 8; nf++) {
            float p0 = ex2(s_acc[nf][0] - nm0);
            float p1 = ex2(s_acc[nf][1] - nm0);
            float p2 = ex2(s_acc[nf][2] - nm1);
            float p3 = ex2(s_acc[nf][3] - nm1);
            sum0 += p0 + p1; sum1 += p2 + p3;
            pa[nf >> 1][(nf & 1) * 2 + 0] = h2u(__floats2half2_rn(p0, p1));
            pa[nf >> 1][(nf & 1) * 2 + 1] = h2u(__floats2half2_rn(p2, p3));
        }
        sum0 += __shfl_xor_sync(0xffffffffu, sum0, 1);
        sum0 += __shfl_xor_sync(0xffffffffu, sum0, 2);
        sum1 += __shfl_xor_sync(0xffffffffu, sum1, 1);
        sum1 += __shfl_xor_sync(0xffffffffu, sum1, 2);
        r_l0 = r_l0 * a0 + sum0;
        r_l1 = r_l1 * a1 + sum1;

        #pragma unroll
        for (int nf = 0; nf < 16; nf++) {
            o_acc[nf][0] *= a0; o_acc[nf][1] *= a0;
            o_acc[nf][2] *= a1; o_acc[nf][3] *= a1;
        }
        #pragma unroll
        for (int hc = 0; hc < 8; hc++) {
            const int cur = hc & 1;
            if (hc + 1 < 8) ldV(hc + 1, vf[cur ^ 1]);
            const int ks = hc >> 1, nh = hc & 1;
            #pragma unroll
            for (int j = 0; j < 4; j++) {
                int np = nh * 4 + j;
                mma_f16(o_acc[np * 2],     pa[ks], vf[cur] + j * 4);
                mma_f16(o_acc[np * 2 + 1], pa[ks], vf[cur] + j * 4 + 2);
            }
        }

        buf = (buf + 1) % NST;
    }

    float inv0 = 1.0f / r_l0, inv1 = 1.0f / r_l1;
    #pragma unroll
    for (int nf = 0; nf < 16; nf++) {
        int col = h * DV + nf * 8 + tig * 2;
        *reinterpret_cast<__half2*>(&O[(size_t)rg0 * ODIM + col]) =
            __floats2half2_rn(o_acc[nf][0] * inv0, o_acc[nf][1] * inv0);
        *reinterpret_cast<__half2*>(&O[(size_t)rg1 * ODIM + col]) =
            __floats2half2_rn(o_acc[nf][2] * inv1, o_acc[nf][3] * inv1);
    }
}

// ---------------- persistent stream/event holder ----------------
struct ForkCtx {
    cudaStream_t sA = 0, sB = 0;
    cudaEvent_t  eFork = 0, eX = 0, eWkvb = 0, eWo = 0, eKV = 0,
                 eQ = 0, eAL = 0, eWL = 0;
    bool ok = false;
    ForkCtx() {
        ok = (cudaStreamCreateWithFlags(&sA, cudaStreamNonBlocking) == cudaSuccess) &&
             (cudaStreamCreateWithFlags(&sB, cudaStreamNonBlocking) == cudaSuccess) &&
             (cudaEventCreateWithFlags(&eFork, cudaEventDisableTiming) == cudaSuccess) &&
             (cudaEventCreateWithFlags(&eX,    cudaEventDisableTiming) == cudaSuccess) &&
             (cudaEventCreateWithFlags(&eWkvb, cudaEventDisableTiming) == cudaSuccess) &&
             (cudaEventCreateWithFlags(&eWo,   cudaEventDisableTiming) == cudaSuccess) &&
             (cudaEventCreateWithFlags(&eKV,   cudaEventDisableTiming) == cudaSuccess) &&
             (cudaEventCreateWithFlags(&eQ,    cudaEventDisableTiming) == cudaSuccess) &&
             (cudaEventCreateWithFlags(&eAL,   cudaEventDisableTiming) == cudaSuccess) &&
             (cudaEventCreateWithFlags(&eWL,   cudaEventDisableTiming) == cudaSuccess);
    }
};

// ---------------- launcher ----------------
extern "C" void kernel_launch(void* const* d_in, const int* in_sizes, int n_in,
                              void* d_out, int out_size)
{
    (void)in_sizes; (void)n_in; (void)out_size;
    const float* x    = (const float*)d_in[0];
    const float* fc   = (const float*)d_in[1];
    const float* fs   = (const float*)d_in[2];
    const float* wq   = (const float*)d_in[4];
    const float* wkva = (const float*)d_in[5];
    const float* kvw  = (const float*)d_in[6];
    const float* wkvb = (const float*)d_in[7];
    const float* wo   = (const float*)d_in[8];
    float* out = (float*)d_out;

    __half *hx, *hwq, *hwkva, *hwkvb, *hwo, *hq, *hkv, *hkvn, *hkpe, *hkvup, *hattn;
    cudaGetSymbolAddress((void**)&hx,    g_hx);
    cudaGetSymbolAddress((void**)&hwq,   g_hwq);
    cudaGetSymbolAddress((void**)&hwkva, g_hwkva);
    cudaGetSymbolAddress((void**)&hwkvb, g_hwkvb);
    cudaGetSymbolAddress((void**)&hwo,   g_hwo);
    cudaGetSymbolAddress((void**)&hq,    g_hq);
    cudaGetSymbolAddress((void**)&hkv,   g_hkv);
    cudaGetSymbolAddress((void**)&hkvn,  g_hkvn);
    cudaGetSymbolAddress((void**)&hkpe,  g_hkpe);
    cudaGetSymbolAddress((void**)&hkvup, g_hkvup);
    cudaGetSymbolAddress((void**)&hattn, g_hattn);

    cudaFuncSetAttribute((const void*)hgemm<true, false>,
        cudaFuncAttributeMaxDynamicSharedMemorySize, (int)sizeof(HGemmSm));
    cudaFuncSetAttribute((const void*)hgemm<true, true>,
        cudaFuncAttributeMaxDynamicSharedMemorySize, (int)sizeof(HGemmSm));
    cudaFuncSetAttribute((const void*)hgemm<false, false>,
        cudaFuncAttributeMaxDynamicSharedMemorySize, (int)sizeof(HGemmSm));
    cudaFuncSetAttribute((const void*)attn_f16,
        cudaFuncAttributeMaxDynamicSharedMemorySize, (int)sizeof(AttnSm));

    static ForkCtx fx;
    const bool forked = fx.ok;
    cudaStream_t sA = forked ? fx.sA : 0;
    cudaStream_t sB = forked ? fx.sB : 0;

    if (forked) {
        cudaEventRecord(fx.eFork, 0);
        cudaStreamWaitEvent(sA, fx.eFork, 0);
        cudaStreamWaitEvent(sB, fx.eFork, 0);
    }

    // ---- stream 0: x convert + Q path (rope fused) ----
    f2h_kernel<<<(S_LEN*DIM_IN) / 1024, 256, 0, 0>>>(x, hx, S_LEN*DIM_IN);
    if (forked) cudaEventRecord(fx.eX, 0);
    f2h_kernel<<<(DIM_IN*QDIM) / 1024, 256, 0, 0>>>(wq, hwq, DIM_IN*QDIM);
    hgemm<true, true><<<dim3(QDIM / 128, S_LEN / 128), 256, sizeof(HGemmSm), 0>>>(
        hx, hwq, hq, S_LEN, QDIM, DIM_IN, fc, fs, 0);
    if (forked) cudaEventRecord(fx.eQ, 0);

    // ---- stream B: independent weight conversions ----
    f2h_kernel<<<(KV_LORA*UPDIM) / 1024, 256, 0, sB>>>(wkvb, hwkvb, KV_LORA*UPDIM);
    if (forked) cudaEventRecord(fx.eWkvb, sB);
    f2h_kernel<<<(ODIM*DIM_IN) / 1024, 256, 0, sB>>>(wo, hwo, ODIM*DIM_IN);
    if (forked) cudaEventRecord(fx.eWo, sB);

    // ---- stream A: KV path ----
    f2h_kernel<<<(DIM_IN*KV_TOT) / 1024, 256, 0, sA>>>(wkva, hwkva, DIM_IN*KV_TOT);
    if (forked) cudaStreamWaitEvent(sA, fx.eX, 0);
    hgemm<true, false><<<dim3((KV_TOT + 127) / 128, S_LEN / 128), 256, sizeof(HGemmSm), sA>>>(
        hx, hwkva, hkv, S_LEN, KV_TOT, DIM_IN, nullptr, nullptr, 0);
    kvnorm_kernel<<<S_LEN, 256, 0, sA>>>(hkv, kvw, fc, fs, hkvn, hkpe);
    if (forked) cudaStreamWaitEvent(sA, fx.eWkvb, 0);
    hgemm<true, false><<<dim3(UPDIM / 128, S_LEN / 128), 256, sizeof(HGemmSm), sA>>>(
        hkvn, hwkvb, hkvup, S_LEN, UPDIM, KV_LORA, nullptr, nullptr, 0);
    if (forked) cudaEventRecord(fx.eKV, sA);

    if (forked) {
        // ---- split attention: heavy half on s0, light half on sA ----
        cudaStreamWaitEvent(0, fx.eKV, 0);
        attn_f16<<<dim3(16, NHEADS), 256, sizeof(AttnSm), 0>>>(
            hq, hkvup, hkpe, hattn, 16);                    // qb 16..31 (rows 2048+)
        // sA already has eKV by program order; needs q:
        cudaStreamWaitEvent(sA, fx.eQ, 0);
        attn_f16<<<dim3(16, NHEADS), 256, sizeof(AttnSm), sA>>>(
            hq, hkvup, hkpe, hattn, 0);                     // qb 0..15
        cudaEventRecord(fx.eAL, sA);

        // ---- woL (rows 0..2047) on sA overlaps attnH tail ----
        cudaStreamWaitEvent(sA, fx.eWo, 0);
        hgemm<false, false><<<dim3(ODIM / 128, 16), 256, sizeof(HGemmSm), sA>>>(
            hattn, hwo, out, S_LEN, ODIM, DIM_IN, nullptr, nullptr, 0);
        cudaEventRecord(fx.eWL, sA);

        // ---- woH (rows 2048..4095) on s0 after attnH ----
        cudaStreamWaitEvent(0, fx.eWo, 0);
        hgemm<false, false><<<dim3(ODIM / 128, 16), 256, sizeof(HGemmSm), 0>>>(
            hattn, hwo, out, S_LEN, ODIM, DIM_IN, nullptr, nullptr, 2048);

        // final join
        cudaStreamWaitEvent(0, fx.eWL, 0);
    } else {
        // serial fallback
        attn_f16<<<dim3(32, NHEADS), 256, sizeof(AttnSm), 0>>>(
            hq, hkvup, hkpe, hattn, 0);
        hgemm<false, false><<<dim3(ODIM / 128, S_LEN / 128), 256, sizeof(HGemmSm), 0>>>(
            hattn, hwo, out, S_LEN, ODIM, DIM_IN, nullptr, nullptr, 0);
    }
}